// round 7
// baseline (speedup 1.0000x reference)
#include <cuda_runtime.h>
#include <math.h>
#include <cstdint>

#define KTOT 2048
#define NJ   40
#define KC   64
#define KCP  68
#define NBIAS 16
#define SMARGIN 0.31f
#define BUFB 45056u          // bytes per smem buffer: x 128*68*4 + W 64*40*4

typedef unsigned long long ull;

// ---- device scratch -------------------------------------------------------
__device__ float g_Wp[KTOT * NJ];
__device__ float g_W12[KTOT * NJ];
__device__ float g_c[NJ];
__device__ float g_cpart[NBIAS * NJ];
__device__ float g_part[8 * KTOT * NJ];

// ---- helpers --------------------------------------------------------------
__device__ __forceinline__ ull pack2(float a, float b) {
    ull r; asm("mov.b64 %0, {%1, %2};" : "=l"(r) : "f"(a), "f"(b)); return r;
}
__device__ __forceinline__ void ffma2(ull& d, ull a, ull b) {
    asm("fma.rn.f32x2 %0, %1, %2, %0;" : "+l"(d) : "l"(a), "l"(b));
}
__device__ __forceinline__ float2 unpack2(ull v) {
    float2 r; asm("mov.b64 {%0, %1}, %2;" : "=f"(r.x), "=f"(r.y) : "l"(v)); return r;
}
__device__ __forceinline__ uint32_t smem_u32(const void* p) {
    uint32_t a;
    asm("{ .reg .u64 t; cvta.to.shared.u64 t, %1; cvt.u32.u64 %0, t; }" : "=r"(a) : "l"(p));
    return a;
}
__device__ __forceinline__ void cp_async16(uint32_t d, const void* s) {
    asm volatile("cp.async.cg.shared.global [%0], [%1], 16;" :: "r"(d), "l"(s));
}
__device__ __forceinline__ void cp_commit() { asm volatile("cp.async.commit_group;" ::: "memory"); }
__device__ __forceinline__ void cp_wait0()  { asm volatile("cp.async.wait_group 0;" ::: "memory"); }

// ---- prep kernels (unchanged, validated) ----------------------------------
__global__ void pack_w_kernel(const float* __restrict__ Wcls, const float* __restrict__ Wfl,
                              const float* __restrict__ bcls, const float* __restrict__ bfl) {
    int i = blockIdx.x * 256 + threadIdx.x;
    if (i < KTOT * NJ) {
        int m = i / NJ, j = i - m * NJ;
        g_Wp[i] = (j < 20) ? Wcls[m * 20 + j] : Wfl[m * 20 + (j - 20)];
    }
    if (i < NJ) g_c[i] = (i < 20) ? bcls[i] : bfl[i - 20];
}

__global__ __launch_bounds__(128)
void bias_kernel(const float* __restrict__ benc) {
    __shared__ float sw[4][NJ];
    int tid = threadIdx.x;
    int k = blockIdx.x * 128 + tid;
    int warp = tid >> 5, lane = tid & 31;
    float b = benc[k];
    const float* wr = g_Wp + (size_t)k * NJ;
    float w[NJ];
#pragma unroll
    for (int j4 = 0; j4 < NJ / 4; j4++) {
        float4 v = *(const float4*)(wr + j4 * 4);
        w[j4*4+0] = v.x; w[j4*4+1] = v.y; w[j4*4+2] = v.z; w[j4*4+3] = v.w;
    }
#pragma unroll
    for (int j = 0; j < NJ; j++) {
        float s = b * w[j];
#pragma unroll
        for (int o = 16; o > 0; o >>= 1) s += __shfl_xor_sync(0xffffffffu, s, o);
        if (lane == 0) sw[warp][j] = s;
    }
    __syncthreads();
    if (tid < NJ) {
        float t = (sw[0][tid] + sw[1][tid]) + (sw[2][tid] + sw[3][tid]);
        g_cpart[blockIdx.x * NJ + tid] = t;
    }
}

__global__ __launch_bounds__(256, 3)
void skinny_gemm_kernel(const float* __restrict__ A, int M) {
    const float* __restrict__ W = g_Wp;
    const int ntiles = M >> 6;
    int tile  = blockIdx.x % ntiles;
    int split = blockIdx.x / ntiles;
    const int kspan = KTOT / 8;
    int kbeg = split * kspan;

    __shared__ float xs[64 * KCP];
    __shared__ float ws[NJ * KCP];

    int tid = threadIdx.x;
    int cg = tid & 7, rg = tid >> 3;
    int j0 = cg * 5, r0 = rg * 2;

    float acc[2][5];
#pragma unroll
    for (int r = 0; r < 2; r++)
#pragma unroll
        for (int j = 0; j < 5; j++) acc[r][j] = 0.f;

    const float* Abase = A + (size_t)(tile * 64) * KTOT + kbeg;

    for (int kc = 0; kc < kspan; kc += KC) {
#pragma unroll
        for (int p = 0; p < 4; p++) {
            int idx = tid + p * 256;
            int row = idx >> 4, c4 = idx & 15;
            float4 v = *(const float4*)(Abase + (size_t)row * KTOT + kc + c4 * 4);
            *(float4*)&xs[row * KCP + c4 * 4] = v;
        }
        {
            const float* Wc = W + (size_t)(kbeg + kc) * NJ;
#pragma unroll
            for (int p = 0; p < 3; p++) {
                int idx = tid + p * 256;
                if (idx < (KC * NJ) / 4) {
                    float4 v = *(const float4*)(Wc + idx * 4);
                    float vv[4] = {v.x, v.y, v.z, v.w};
#pragma unroll
                    for (int e = 0; e < 4; e++) {
                        int el = idx * 4 + e;
                        int k = el / NJ, j = el - k * NJ;
                        ws[j * KCP + k] = vv[e];
                    }
                }
            }
        }
        __syncthreads();
#pragma unroll
        for (int k4 = 0; k4 < KC / 4; k4++) {
            float4 x0 = *(const float4*)&xs[(r0 + 0) * KCP + k4 * 4];
            float4 x1 = *(const float4*)&xs[(r0 + 1) * KCP + k4 * 4];
#pragma unroll
            for (int jj = 0; jj < 5; jj++) {
                float4 w = *(const float4*)&ws[(j0 + jj) * KCP + k4 * 4];
                acc[0][jj] += x0.x * w.x; acc[0][jj] += x0.y * w.y;
                acc[0][jj] += x0.z * w.z; acc[0][jj] += x0.w * w.w;
                acc[1][jj] += x1.x * w.x; acc[1][jj] += x1.y * w.y;
                acc[1][jj] += x1.z * w.z; acc[1][jj] += x1.w * w.w;
            }
        }
        __syncthreads();
    }

    float* o = g_part + ((size_t)split * M + tile * 64) * NJ;
#pragma unroll
    for (int r = 0; r < 2; r++)
#pragma unroll
        for (int jj = 0; jj < 5; jj++)
            o[(r0 + r) * NJ + j0 + jj] = acc[r][jj];
}

__global__ void reduce_w12_kernel() {
    int i = blockIdx.x * 256 + threadIdx.x;
    if (i < KTOT * NJ) {
        float s = 0.f;
#pragma unroll
        for (int p = 0; p < 8; p++) s += g_part[p * (KTOT * NJ) + i];
        g_W12[i] = s;
    }
}

// ---- main kernel ----------------------------------------------------------
// grid 128, block 256 (8 warps = 2/SMSP).  Warp w covers rows [16w,16w+16),
// lanes 0-15 -> col half 0 (cls), lanes 16-31 -> half 1 (flow).
// Thread: 1 row-half, acc = 10 f32x2.  Double-buffered cp.async staging.
__device__ __forceinline__ void stage_chunk(uint32_t smb, int buf, int c,
                                            const float* __restrict__ x,
                                            size_t growbase, int tid) {
    uint32_t xd = smb + (uint32_t)buf * BUFB;
#pragma unroll
    for (int it = 0; it < 8; it++) {
        int q = it * 256 + tid;
        int rw = q >> 4, c4 = q & 15;
        cp_async16(xd + (uint32_t)(rw * 272 + c4 * 16),
                   x + (growbase + rw) * KTOT + c * 64 + c4 * 4);
    }
    uint32_t wd = xd + 34816u;
    const float* wsrc = g_W12 + (size_t)c * 2560;
#pragma unroll
    for (int it = 0; it < 3; it++) {
        int q = it * 256 + tid;
        if (q < 640) cp_async16(wd + (uint32_t)q * 16, wsrc + q * 4);
    }
}

__global__ __launch_bounds__(256, 1)
void f32x2_main_kernel(const float* __restrict__ x, float* __restrict__ out) {
    extern __shared__ float sm[];
    __shared__ float cb[NJ];
    const int tid = threadIdx.x;
    const int warp = tid >> 5, lane = tid & 31;
    const int half = lane >> 4;                 // 0: cols 0-19, 1: cols 20-39
    const int rl = warp * 16 + (lane & 15);     // local row 0..127
    const size_t growbase = (size_t)blockIdx.x * 128;

    if (tid < NJ) {
        float s = g_c[tid];
#pragma unroll
        for (int p = 0; p < NBIAS; p++) s += g_cpart[p * NJ + tid];
        cb[tid] = s;
    }

    const uint32_t smb = smem_u32(sm);
    stage_chunk(smb, 0, 0, x, growbase, tid);
    cp_commit(); cp_wait0();
    __syncthreads();

    ull acc[10];
#pragma unroll
    for (int p = 0; p < 10; p++) acc[p] = pack2(0.f, 0.f);

    for (int c = 0; c < 32; c++) {
        int buf = c & 1;
        if (c + 1 < 32) { stage_chunk(smb, buf ^ 1, c + 1, x, growbase, tid); cp_commit(); }
        uint32_t base = smb + (uint32_t)buf * BUFB;
        uint32_t xa = base + (uint32_t)(rl * 272);
        uint32_t wa = base + 34816u + (uint32_t)(half * 80);
#pragma unroll 8
        for (int k = 0; k < 64; k++) {
            float a;
            asm("ld.shared.f32 %0, [%1];" : "=f"(a) : "r"(xa + k * 4));
            ull p0 = pack2(a, a);
#pragma unroll
            for (int p = 0; p < 5; p++) {
                ull w0, w1;
                asm("ld.shared.v2.u64 {%0, %1}, [%2];"
                    : "=l"(w0), "=l"(w1) : "r"(wa + k * 160 + p * 16));
                ffma2(acc[p * 2], p0, w0);
                ffma2(acc[p * 2 + 1], p0, w1);
            }
        }
        if (c + 1 < 32) cp_wait0();
        __syncthreads();
    }

    // ---- epilogue: bias + dual softmax + threshold -----------------------
    float lg[20];
#pragma unroll
    for (int j = 0; j < 10; j++) {
        float2 t = unpack2(acc[j]);
        lg[2 * j]     = t.x + cb[half * 20 + 2 * j];
        lg[2 * j + 1] = t.y + cb[half * 20 + 2 * j + 1];
    }

    float pred = 0.f, tauv = 0.f;
    float e[20];
    if (half == 0) {            // cls softmax
        float m1 = lg[0];
#pragma unroll
        for (int j = 1; j < 20; j++) m1 = fmaxf(m1, lg[j]);
        float s1 = 0.f;
#pragma unroll
        for (int j = 0; j < 20; j++) { e[j] = __expf(lg[j] - m1); s1 += e[j]; }
        pred = 1.f / s1;
    } else {                    // flow softmax min -> tau
        float m2 = lg[0], mn2 = lg[0];
#pragma unroll
        for (int j = 1; j < 20; j++) { m2 = fmaxf(m2, lg[j]); mn2 = fminf(mn2, lg[j]); }
        float s2 = 0.f;
#pragma unroll
        for (int j = 0; j < 20; j++) s2 += __expf(lg[j] - m2);
        tauv = __expf(mn2 - m2) / s2;
    }
    float tau = __shfl_xor_sync(0xffffffffu, tauv, 16);
    if (half == 0) {
        float scl = (pred >= tau + SMARGIN) ? pred : 0.f;
        float* o = out + (growbase + rl) * 20;
#pragma unroll
        for (int j = 0; j < 10; j++)
            *(float2*)(o + 2 * j) = make_float2(e[2 * j] * scl, e[2 * j + 1] * scl);
    }
}

// ---------------------------------------------------------------------------
extern "C" void kernel_launch(void* const* d_in, const int* in_sizes, int n_in,
                              void* d_out, int out_size) {
    const float* x    = (const float*)d_in[0];
    const float* Wenc = (const float*)d_in[1];
    const float* benc = (const float*)d_in[2];
    const float* Wcls = (const float*)d_in[3];
    const float* bcls = (const float*)d_in[4];
    const float* Wfl  = (const float*)d_in[5];
    const float* bfl  = (const float*)d_in[6];
    float* out = (float*)d_out;
    int M = in_sizes[0] / KTOT;   // 16384

    static int smset = 0;
    if (!smset) {
        cudaFuncSetAttribute(f32x2_main_kernel,
                             cudaFuncAttributeMaxDynamicSharedMemorySize, 2 * BUFB);
        smset = 1;
    }

    pack_w_kernel<<<(KTOT * NJ + 255) / 256, 256>>>(Wcls, Wfl, bcls, bfl);
    skinny_gemm_kernel<<<(KTOT / 64) * 8, 256>>>(Wenc, KTOT);
    reduce_w12_kernel<<<(KTOT * NJ + 255) / 256, 256>>>();
    bias_kernel<<<NBIAS, 128>>>(benc);
    f32x2_main_kernel<<<M / 128, 256, 2 * BUFB>>>(x, out);
}

// round 8
// speedup vs baseline: 1.9936x; 1.9936x over previous
#include <cuda_runtime.h>
#include <cuda_bf16.h>
#include <math.h>
#include <cstdint>

#define KTOT 2048
#define NJ   40
#define NT   5
#define NKC  128            // 2048/16 k-steps total
#define KC   64
#define KCP  68
#define NBIAS 16
#define SMARGIN 0.31f
#define XBYTES 34816u       // 128 rows * 272 B
#define BBYTES 10240u       // 640 uint2 hi + 640 uint2 lo
#define BUFB   (XBYTES + BBYTES)

// ---- device scratch -------------------------------------------------------
__device__ float g_c[NJ];
__device__ float g_cpart[NBIAS * NJ];
__device__ float g_part[8 * KTOT * NJ];
__device__ uint2 g_Bfh[NKC * NT * 32];
__device__ uint2 g_Bfl[NKC * NT * 32];

// ---- helpers --------------------------------------------------------------
__device__ __forceinline__ uint32_t smem_u32(const void* p) {
    uint32_t a;
    asm("{ .reg .u64 t; cvta.to.shared.u64 t, %1; cvt.u32.u64 %0, t; }" : "=r"(a) : "l"(p));
    return a;
}
__device__ __forceinline__ void cp_async16(uint32_t d, const void* s) {
    asm volatile("cp.async.cg.shared.global [%0], [%1], 16;" :: "r"(d), "l"(s));
}
__device__ __forceinline__ void cp_commit() { asm volatile("cp.async.commit_group;" ::: "memory"); }
__device__ __forceinline__ void cp_wait0()  { asm volatile("cp.async.wait_group 0;" ::: "memory"); }

#define MMA_BF16(d, a0, a1, a2, a3, b0, b1)                                   \
    asm volatile("mma.sync.aligned.m16n8k16.row.col.f32.bf16.bf16.f32 "       \
                 "{%0,%1,%2,%3}, {%4,%5,%6,%7}, {%8,%9}, {%0,%1,%2,%3};\n"    \
                 : "+f"(d[0]), "+f"(d[1]), "+f"(d[2]), "+f"(d[3])             \
                 : "r"(a0), "r"(a1), "r"(a2), "r"(a3), "r"(b0), "r"(b1))

__device__ __forceinline__ void cvt_split(float2 v, unsigned& h, unsigned& l) {
    __nv_bfloat162 hb = __float22bfloat162_rn(make_float2(v.x, v.y));
    float rx = v.x - __bfloat162float(hb.x);
    float ry = v.y - __bfloat162float(hb.y);
    __nv_bfloat162 lb = __float22bfloat162_rn(make_float2(rx, ry));
    h = *reinterpret_cast<unsigned*>(&hb);
    l = *reinterpret_cast<unsigned*>(&lb);
}
__device__ __forceinline__ unsigned pack_bf2(float a, float b) {
    __nv_bfloat162 h = __float22bfloat162_rn(make_float2(a, b));
    return *reinterpret_cast<unsigned*>(&h);
}
__device__ __forceinline__ float bf_res(float v) {
    __nv_bfloat16 h = __float2bfloat16_rn(v);
    return v - __bfloat162float(h);
}

// ---------------------------------------------------------------------------
// Prep 1: W12 partials = W_enc @ [Wcls|Wfl] (pack fused into staging), K-split 8
// ---------------------------------------------------------------------------
__global__ __launch_bounds__(256, 3)
void skinny_gemm_kernel(const float* __restrict__ A,
                        const float* __restrict__ Wcls, const float* __restrict__ Wfl) {
    const int M = KTOT;
    const int ntiles = M >> 6;
    int tile  = blockIdx.x % ntiles;
    int split = blockIdx.x / ntiles;
    const int kspan = KTOT / 8;
    int kbeg = split * kspan;

    __shared__ float xs[64 * KCP];
    __shared__ float ws[NJ * KCP];

    int tid = threadIdx.x;
    int cg = tid & 7, rg = tid >> 3;
    int j0 = cg * 5, r0 = rg * 2;

    float acc[2][5];
#pragma unroll
    for (int r = 0; r < 2; r++)
#pragma unroll
        for (int j = 0; j < 5; j++) acc[r][j] = 0.f;

    const float* Abase = A + (size_t)(tile * 64) * KTOT + kbeg;

    for (int kc = 0; kc < kspan; kc += KC) {
#pragma unroll
        for (int p = 0; p < 4; p++) {
            int idx = tid + p * 256;
            int row = idx >> 4, c4 = idx & 15;
            float4 v = *(const float4*)(Abase + (size_t)row * KTOT + kc + c4 * 4);
            *(float4*)&xs[row * KCP + c4 * 4] = v;
        }
#pragma unroll
        for (int p = 0; p < 3; p++) {
            int idx = tid + p * 256;
            if (idx < 640) {
                int k = idx / 10, j4 = idx - k * 10;
                const float* src = (j4 < 5) ? (Wcls + (size_t)(kbeg + kc + k) * 20 + j4 * 4)
                                            : (Wfl  + (size_t)(kbeg + kc + k) * 20 + (j4 - 5) * 4);
                float4 v = *(const float4*)src;
                int jb = j4 * 4;
                ws[(jb + 0) * KCP + k] = v.x;
                ws[(jb + 1) * KCP + k] = v.y;
                ws[(jb + 2) * KCP + k] = v.z;
                ws[(jb + 3) * KCP + k] = v.w;
            }
        }
        __syncthreads();
#pragma unroll
        for (int k4 = 0; k4 < KC / 4; k4++) {
            float4 x0 = *(const float4*)&xs[(r0 + 0) * KCP + k4 * 4];
            float4 x1 = *(const float4*)&xs[(r0 + 1) * KCP + k4 * 4];
#pragma unroll
            for (int jj = 0; jj < 5; jj++) {
                float4 w = *(const float4*)&ws[(j0 + jj) * KCP + k4 * 4];
                acc[0][jj] += x0.x * w.x; acc[0][jj] += x0.y * w.y;
                acc[0][jj] += x0.z * w.z; acc[0][jj] += x0.w * w.w;
                acc[1][jj] += x1.x * w.x; acc[1][jj] += x1.y * w.y;
                acc[1][jj] += x1.z * w.z; acc[1][jj] += x1.w * w.w;
            }
        }
        __syncthreads();
    }

    float* o = g_part + ((size_t)split * M + tile * 64) * NJ;
#pragma unroll
    for (int r = 0; r < 2; r++)
#pragma unroll
        for (int jj = 0; jj < 5; jj++)
            o[(r0 + r) * NJ + j0 + jj] = acc[r][jj];
}

// ---------------------------------------------------------------------------
// Prep 2: blocks 0..79 reduce partials -> bf16 hi/lo fragments;
//         blocks 80..95 bias partials; block 80 also inits g_c raw biases.
// ---------------------------------------------------------------------------
__global__ __launch_bounds__(256)
void bsplit_bias_kernel(const float* __restrict__ benc,
                        const float* __restrict__ Wcls, const float* __restrict__ Wfl,
                        const float* __restrict__ bcls, const float* __restrict__ bfl) {
    int b = blockIdx.x;
    int tid = threadIdx.x;
    if (b < 80) {
        int idx = b * 256 + tid;                 // frag index 0..20479
        int kc16 = idx / 160;
        int rem = idx - kc16 * 160;
        int nt = rem >> 5, lane = rem & 31;
        int k0 = kc16 * 16 + (lane & 3) * 2;
        int n  = nt * 8 + (lane >> 2);
        float v[4];
#pragma unroll
        for (int e = 0; e < 4; e++) {
            int k = k0 + (e >> 1) * 8 + (e & 1);
            float s = 0.f;
#pragma unroll
            for (int p = 0; p < 8; p++) s += g_part[(size_t)p * (KTOT * NJ) + k * NJ + n];
            v[e] = s;
        }
        g_Bfh[idx] = make_uint2(pack_bf2(v[0], v[1]), pack_bf2(v[2], v[3]));
        g_Bfl[idx] = make_uint2(pack_bf2(bf_res(v[0]), bf_res(v[1])),
                                pack_bf2(bf_res(v[2]), bf_res(v[3])));
        return;
    }
    // bias blocks: 16 blocks x 128 active threads cover k = 0..2047
    __shared__ float sw[4][NJ];
    int bb = b - 80;
    if (tid >= 128) return;
    int k = bb * 128 + tid;
    int warp = tid >> 5, lane = tid & 31;
    float bv = benc[k];
    float w[NJ];
#pragma unroll
    for (int j4 = 0; j4 < 5; j4++) {
        float4 v = *(const float4*)(Wcls + (size_t)k * 20 + j4 * 4);
        w[j4*4+0] = v.x; w[j4*4+1] = v.y; w[j4*4+2] = v.z; w[j4*4+3] = v.w;
    }
#pragma unroll
    for (int j4 = 0; j4 < 5; j4++) {
        float4 v = *(const float4*)(Wfl + (size_t)k * 20 + j4 * 4);
        w[20+j4*4+0] = v.x; w[20+j4*4+1] = v.y; w[20+j4*4+2] = v.z; w[20+j4*4+3] = v.w;
    }
#pragma unroll
    for (int j = 0; j < NJ; j++) {
        float s = bv * w[j];
#pragma unroll
        for (int o = 16; o > 0; o >>= 1) s += __shfl_xor_sync(0xffffffffu, s, o);
        if (lane == 0) sw[warp][j] = s;
    }
    __syncthreads();
    if (tid < NJ) {
        g_cpart[bb * NJ + tid] = (sw[0][tid] + sw[1][tid]) + (sw[2][tid] + sw[3][tid]);
        if (bb == 0) g_c[tid] = (tid < 20) ? bcls[tid] : bfl[tid - 20];
    }
}

// ---------------------------------------------------------------------------
// Main kernel: 128 rows x 40 cols per CTA via bf16 hi/lo mma.sync,
// x staged fp32 via double-buffered cp.async, fused dual-softmax epilogue.
// ---------------------------------------------------------------------------
__device__ __forceinline__ void stage_chunk(uint32_t smb, int buf, int c,
                                            const float* __restrict__ x,
                                            size_t growbase, int tid) {
    uint32_t xd = smb + (uint32_t)buf * BUFB;
#pragma unroll
    for (int it = 0; it < 8; it++) {
        int q = it * 256 + tid;
        int rw = q >> 4, c4 = q & 15;
        cp_async16(xd + (uint32_t)(rw * 272 + c4 * 16),
                   x + (growbase + rw) * KTOT + c * 64 + c4 * 4);
    }
    uint32_t bd = xd + XBYTES;
    const char* srcH = (const char*)(g_Bfh + (size_t)c * 640);
    const char* srcL = (const char*)(g_Bfl + (size_t)c * 640);
#pragma unroll
    for (int it = 0; it < 3; it++) {
        int q = it * 256 + tid;
        if (q < 320)      cp_async16(bd + (uint32_t)q * 16, srcH + q * 16);
        else if (q < 640) cp_async16(bd + 5120u + (uint32_t)(q - 320) * 16, srcL + (q - 320) * 16);
    }
}

__global__ __launch_bounds__(256, 1)
void mma_main_kernel(const float* __restrict__ x, float* __restrict__ out) {
    extern __shared__ char sm[];
    __shared__ float cb[NJ];
    const int tid = threadIdx.x;
    const int warp = tid >> 5, lane = tid & 31;
    const int c2 = (lane & 3) * 2;
    const size_t growbase = (size_t)blockIdx.x * 128;

    if (tid < NJ) {
        float s = g_c[tid];
#pragma unroll
        for (int p = 0; p < NBIAS; p++) s += g_cpart[p * NJ + tid];
        cb[tid] = s;
    }

    const uint32_t smb = smem_u32(sm);
    stage_chunk(smb, 0, 0, x, growbase, tid);
    cp_commit(); cp_wait0();
    __syncthreads();

    float acc[NT][4];
#pragma unroll
    for (int nt = 0; nt < NT; nt++)
#pragma unroll
        for (int e = 0; e < 4; e++) acc[nt][e] = 0.f;

    // x byte addr of this thread's row within a buffer
    const uint32_t xoff = (uint32_t)((warp * 16 + (lane >> 2)) * 272 + c2 * 4);

    for (int c = 0; c < 32; c++) {
        int buf = c & 1;
        if (c + 1 < 32) { stage_chunk(smb, buf ^ 1, c + 1, x, growbase, tid); cp_commit(); }
        uint32_t base = smb + (uint32_t)buf * BUFB;
        uint32_t xa = base + xoff;
        uint32_t ba = base + XBYTES + (uint32_t)lane * 8;
#pragma unroll
        for (int s = 0; s < 4; s++) {
            float2 v00, v10, v01, v11;
            asm("ld.shared.v2.f32 {%0, %1}, [%2];" : "=f"(v00.x), "=f"(v00.y) : "r"(xa + s * 64));
            asm("ld.shared.v2.f32 {%0, %1}, [%2];" : "=f"(v10.x), "=f"(v10.y) : "r"(xa + s * 64 + 8 * 272));
            asm("ld.shared.v2.f32 {%0, %1}, [%2];" : "=f"(v01.x), "=f"(v01.y) : "r"(xa + s * 64 + 32));
            asm("ld.shared.v2.f32 {%0, %1}, [%2];" : "=f"(v11.x), "=f"(v11.y) : "r"(xa + s * 64 + 32 + 8 * 272));
            unsigned ah0, ah1, ah2, ah3, al0, al1, al2, al3;
            cvt_split(v00, ah0, al0);
            cvt_split(v10, ah1, al1);
            cvt_split(v01, ah2, al2);
            cvt_split(v11, ah3, al3);
#pragma unroll
            for (int nt = 0; nt < NT; nt++) {
                uint2 wh, wl;
                uint32_t fo = (uint32_t)((s * NT + nt) * 32) * 8;
                asm("ld.shared.v2.u32 {%0, %1}, [%2];" : "=r"(wh.x), "=r"(wh.y) : "r"(ba + fo));
                asm("ld.shared.v2.u32 {%0, %1}, [%2];" : "=r"(wl.x), "=r"(wl.y) : "r"(ba + fo + 5120));
                MMA_BF16(acc[nt], ah0, ah1, ah2, ah3, wh.x, wh.y);
                MMA_BF16(acc[nt], al0, al1, al2, al3, wh.x, wh.y);
                MMA_BF16(acc[nt], ah0, ah1, ah2, ah3, wl.x, wl.y);
            }
        }
        if (c + 1 < 32) cp_wait0();
        __syncthreads();
    }

    // ---- epilogue (validated in R3): dual softmax + threshold ------------
    int row0 = (int)growbase + warp * 16 + (lane >> 2);
    float scl[2];
    float ecls[2][6];
#pragma unroll
    for (int half = 0; half < 2; half++) {
        float m1 = -1e30f, m2 = -1e30f, mn2 = 1e30f;
#pragma unroll
        for (int nt = 0; nt < NT; nt++)
#pragma unroll
            for (int e = 0; e < 2; e++) {
                int j = nt * 8 + c2 + e;
                float v = acc[nt][half * 2 + e] + cb[j];
                if (j < 20) m1 = fmaxf(m1, v);
                else { m2 = fmaxf(m2, v); mn2 = fminf(mn2, v); }
            }
        m1 = fmaxf(m1, __shfl_xor_sync(0xffffffffu, m1, 1));
        m1 = fmaxf(m1, __shfl_xor_sync(0xffffffffu, m1, 2));
        m2 = fmaxf(m2, __shfl_xor_sync(0xffffffffu, m2, 1));
        m2 = fmaxf(m2, __shfl_xor_sync(0xffffffffu, m2, 2));
        mn2 = fminf(mn2, __shfl_xor_sync(0xffffffffu, mn2, 1));
        mn2 = fminf(mn2, __shfl_xor_sync(0xffffffffu, mn2, 2));
        float s1 = 0.f, s2 = 0.f;
#pragma unroll
        for (int nt = 0; nt < NT; nt++)
#pragma unroll
            for (int e = 0; e < 2; e++) {
                int j = nt * 8 + c2 + e;
                float v = acc[nt][half * 2 + e] + cb[j];
                if (j < 20) {
                    float ex = __expf(v - m1);
                    if (nt < 3) ecls[half][nt * 2 + e] = ex;
                    s1 += ex;
                } else {
                    s2 += __expf(v - m2);
                }
            }
        s1 += __shfl_xor_sync(0xffffffffu, s1, 1);
        s1 += __shfl_xor_sync(0xffffffffu, s1, 2);
        s2 += __shfl_xor_sync(0xffffffffu, s2, 1);
        s2 += __shfl_xor_sync(0xffffffffu, s2, 2);
        float pred = 1.0f / s1;
        float tau  = __expf(mn2 - m2) / s2;
        scl[half] = (pred >= tau + SMARGIN) ? pred : 0.0f;
    }
#pragma unroll
    for (int half = 0; half < 2; half++) {
        float* orow = out + (size_t)(row0 + half * 8) * 20;
#pragma unroll
        for (int nt = 0; nt < 3; nt++) {
            int j0 = nt * 8 + c2;
            if (j0 < 20)
                *(float2*)(orow + j0) = make_float2(ecls[half][nt * 2 + 0] * scl[half],
                                                    ecls[half][nt * 2 + 1] * scl[half]);
        }
    }
}

// ---------------------------------------------------------------------------
extern "C" void kernel_launch(void* const* d_in, const int* in_sizes, int n_in,
                              void* d_out, int out_size) {
    const float* x    = (const float*)d_in[0];
    const float* Wenc = (const float*)d_in[1];
    const float* benc = (const float*)d_in[2];
    const float* Wcls = (const float*)d_in[3];
    const float* bcls = (const float*)d_in[4];
    const float* Wfl  = (const float*)d_in[5];
    const float* bfl  = (const float*)d_in[6];
    float* out = (float*)d_out;
    int M = in_sizes[0] / KTOT;   // 16384

    static int smset = 0;
    if (!smset) {
        cudaFuncSetAttribute(mma_main_kernel,
                             cudaFuncAttributeMaxDynamicSharedMemorySize, 2 * BUFB);
        smset = 1;
    }

    skinny_gemm_kernel<<<(KTOT / 64) * 8, 256>>>(Wenc, Wcls, Wfl);
    bsplit_bias_kernel<<<96, 256>>>(benc, Wcls, Wfl, bcls, bfl);
    mma_main_kernel<<<M / 128, 256, 2 * BUFB>>>(x, out);
}

// round 9
// speedup vs baseline: 2.3333x; 1.1704x over previous
#include <cuda_runtime.h>
#include <cuda_fp16.h>
#include <math.h>
#include <cstdint>

#define KTOT 2048
#define NJ   40
#define NT   5
#define NKC  128            // 2048/16 k-steps total
#define NBIAS 16
#define SMARGIN 0.31f
#define RSCALE 2048.0f      // residual scale 2^11
#define RINV   (1.0f / 2048.0f)
#define XBYTES 34816u       // 128 rows * 272 B
#define BBYTES 10240u       // frag buf (main) / fp32 Wp slab (prep)
#define BUFB   (XBYTES + BBYTES)

// ---- device scratch -------------------------------------------------------
__device__ float g_c[NJ];
__device__ float g_cpart[NBIAS * NJ];
__device__ float g_part[8 * KTOT * NJ];
__device__ uint2 g_Bfh[NKC * NT * 32];   // fp16 hi fragments
__device__ uint2 g_Bfl[NKC * NT * 32];   // fp16 residual*2048 fragments

// ---- helpers --------------------------------------------------------------
__device__ __forceinline__ uint32_t smem_u32(const void* p) {
    uint32_t a;
    asm("{ .reg .u64 t; cvta.to.shared.u64 t, %1; cvt.u32.u64 %0, t; }" : "=r"(a) : "l"(p));
    return a;
}
__device__ __forceinline__ void cp_async16(uint32_t d, const void* s) {
    asm volatile("cp.async.cg.shared.global [%0], [%1], 16;" :: "r"(d), "l"(s));
}
__device__ __forceinline__ void cp_commit() { asm volatile("cp.async.commit_group;" ::: "memory"); }
__device__ __forceinline__ void cp_wait0()  { asm volatile("cp.async.wait_group 0;" ::: "memory"); }

#define MMA_F16(d, a0, a1, a2, a3, b0, b1)                                    \
    asm volatile("mma.sync.aligned.m16n8k16.row.col.f32.f16.f16.f32 "         \
                 "{%0,%1,%2,%3}, {%4,%5,%6,%7}, {%8,%9}, {%0,%1,%2,%3};\n"    \
                 : "+f"(d[0]), "+f"(d[1]), "+f"(d[2]), "+f"(d[3])             \
                 : "r"(a0), "r"(a1), "r"(a2), "r"(a3), "r"(b0), "r"(b1))

// fp16 hi + scaled residual split: v = h + (l/2048), each fp16-exact
__device__ __forceinline__ void cvt_split_h(float2 v, unsigned& h, unsigned& l) {
    __half2 hh = __floats2half2_rn(v.x, v.y);
    float2 hf = __half22float2(hh);
    __half2 ll = __floats2half2_rn((v.x - hf.x) * RSCALE, (v.y - hf.y) * RSCALE);
    h = *reinterpret_cast<unsigned*>(&hh);
    l = *reinterpret_cast<unsigned*>(&ll);
}
__device__ __forceinline__ unsigned pack_h2(float a, float b) {
    __half2 h = __floats2half2_rn(a, b);
    return *reinterpret_cast<unsigned*>(&h);
}

// ---------------------------------------------------------------------------
// Prep 1 (mma): g_part[split] = W_enc @ [Wcls|Wfl] over m in [split*256,+256)
// grid 128 = 16 row-tiles x 8 splits, 256 thr.  fp16 3-term split, fp32 out.
// ---------------------------------------------------------------------------
__device__ __forceinline__ void prep_stage(uint32_t smb, int buf, int koff,
                                           const float* __restrict__ Wenc, int tilebase,
                                           const float* __restrict__ Wcls,
                                           const float* __restrict__ Wfl, int tid) {
    uint32_t xd = smb + (uint32_t)buf * BUFB;
#pragma unroll
    for (int it = 0; it < 8; it++) {
        int q = it * 256 + tid;
        int rw = q >> 4, c4 = q & 15;
        cp_async16(xd + (uint32_t)(rw * 272 + c4 * 16),
                   Wenc + (size_t)(tilebase + rw) * KTOT + koff + c4 * 4);
    }
    uint32_t wd = xd + XBYTES;
#pragma unroll
    for (int it = 0; it < 3; it++) {
        int q = it * 256 + tid;
        if (q < 640) {
            int k = q / 10, j4 = q - k * 10;
            const float* src = (j4 < 5) ? (Wcls + (size_t)(koff + k) * 20 + j4 * 4)
                                        : (Wfl  + (size_t)(koff + k) * 20 + (j4 - 5) * 4);
            cp_async16(wd + (uint32_t)(k * 160 + j4 * 16), src);
        }
    }
}

__global__ __launch_bounds__(256, 1)
void prep_mma_kernel(const float* __restrict__ Wenc,
                     const float* __restrict__ Wcls, const float* __restrict__ Wfl) {
    extern __shared__ char sm[];
    const int tid = threadIdx.x;
    const int warp = tid >> 5, lane = tid & 31;
    const int c2 = (lane & 3) * 2;
    const int tile = blockIdx.x & 15, split = blockIdx.x >> 4;
    const int tilebase = tile * 128;
    const int kbeg = split * 256;

    const uint32_t smb = smem_u32(sm);
    prep_stage(smb, 0, kbeg, Wenc, tilebase, Wcls, Wfl, tid);
    cp_commit(); cp_wait0();
    __syncthreads();

    float acc1[NT][4], acc2[NT][4];
#pragma unroll
    for (int nt = 0; nt < NT; nt++)
#pragma unroll
        for (int e = 0; e < 4; e++) { acc1[nt][e] = 0.f; acc2[nt][e] = 0.f; }

    const uint32_t xoff = (uint32_t)((warp * 16 + (lane >> 2)) * 272 + c2 * 4);
    const uint32_t woff = (uint32_t)(((lane & 3) * 2 * 40 + (lane >> 2)) * 4);

    for (int c = 0; c < 4; c++) {
        int buf = c & 1;
        if (c + 1 < 4) {
            prep_stage(smb, buf ^ 1, kbeg + (c + 1) * 64, Wenc, tilebase, Wcls, Wfl, tid);
            cp_commit();
        }
        uint32_t base = smb + (uint32_t)buf * BUFB;
        uint32_t xa = base + xoff;
        uint32_t wsb = base + XBYTES + woff;
#pragma unroll
        for (int s = 0; s < 4; s++) {
            float2 v00, v10, v01, v11;
            asm("ld.shared.v2.f32 {%0, %1}, [%2];" : "=f"(v00.x), "=f"(v00.y) : "r"(xa + s * 64));
            asm("ld.shared.v2.f32 {%0, %1}, [%2];" : "=f"(v10.x), "=f"(v10.y) : "r"(xa + s * 64 + 8 * 272));
            asm("ld.shared.v2.f32 {%0, %1}, [%2];" : "=f"(v01.x), "=f"(v01.y) : "r"(xa + s * 64 + 32));
            asm("ld.shared.v2.f32 {%0, %1}, [%2];" : "=f"(v11.x), "=f"(v11.y) : "r"(xa + s * 64 + 32 + 8 * 272));
            unsigned ah0, ah1, ah2, ah3, al0, al1, al2, al3;
            cvt_split_h(v00, ah0, al0);
            cvt_split_h(v10, ah1, al1);
            cvt_split_h(v01, ah2, al2);
            cvt_split_h(v11, ah3, al3);
            uint32_t ka = wsb + (uint32_t)(s * 16 * 160);
#pragma unroll
            for (int nt = 0; nt < NT; nt++) {
                float w00, w01, w10, w11;
                uint32_t a = ka + (uint32_t)(nt * 32);
                asm("ld.shared.f32 %0, [%1];" : "=f"(w00) : "r"(a));
                asm("ld.shared.f32 %0, [%1];" : "=f"(w01) : "r"(a + 160));
                asm("ld.shared.f32 %0, [%1];" : "=f"(w10) : "r"(a + 8 * 160));
                asm("ld.shared.f32 %0, [%1];" : "=f"(w11) : "r"(a + 9 * 160));
                unsigned bh0, bl0, bh1, bl1;
                cvt_split_h(make_float2(w00, w01), bh0, bl0);
                cvt_split_h(make_float2(w10, w11), bh1, bl1);
                MMA_F16(acc1[nt], ah0, ah1, ah2, ah3, bh0, bh1);
                MMA_F16(acc2[nt], al0, al1, al2, al3, bh0, bh1);
                MMA_F16(acc2[nt], ah0, ah1, ah2, ah3, bl0, bl1);
            }
        }
        if (c + 1 < 4) cp_wait0();
        __syncthreads();
    }

    // write fp32 partials: rows = W12 k index, cols = n
    int krow = tilebase + warp * 16 + (lane >> 2);
#pragma unroll
    for (int nt = 0; nt < NT; nt++) {
        float* p0 = g_part + ((size_t)split * KTOT + krow) * NJ + nt * 8 + c2;
        float* p1 = p0 + 8 * NJ;
        *(float2*)p0 = make_float2(acc1[nt][0] + acc2[nt][0] * RINV,
                                   acc1[nt][1] + acc2[nt][1] * RINV);
        *(float2*)p1 = make_float2(acc1[nt][2] + acc2[nt][2] * RINV,
                                   acc1[nt][3] + acc2[nt][3] * RINV);
    }
}

// ---------------------------------------------------------------------------
// Prep 2: blocks 0..79 reduce partials -> fp16 hi / scaled-lo fragments;
//         blocks 80..95 bias partials; block 80 inits g_c raw biases.
// ---------------------------------------------------------------------------
__global__ __launch_bounds__(256)
void bsplit_bias_kernel(const float* __restrict__ benc,
                        const float* __restrict__ Wcls, const float* __restrict__ Wfl,
                        const float* __restrict__ bcls, const float* __restrict__ bfl) {
    int b = blockIdx.x;
    int tid = threadIdx.x;
    if (b < 80) {
        int idx = b * 256 + tid;                 // frag index 0..20479
        int kc16 = idx / 160;
        int rem = idx - kc16 * 160;
        int nt = rem >> 5, lane = rem & 31;
        int k0 = kc16 * 16 + (lane & 3) * 2;
        int n  = nt * 8 + (lane >> 2);
        float v[4];
#pragma unroll
        for (int e = 0; e < 4; e++) {
            int k = k0 + (e >> 1) * 8 + (e & 1);
            float s = 0.f;
#pragma unroll
            for (int p = 0; p < 8; p++) s += g_part[(size_t)p * (KTOT * NJ) + k * NJ + n];
            v[e] = s;
        }
        float r[4];
#pragma unroll
        for (int e = 0; e < 4; e++) {
            __half h = __float2half_rn(v[e]);
            r[e] = (v[e] - __half2float(h)) * RSCALE;
        }
        g_Bfh[idx] = make_uint2(pack_h2(v[0], v[1]), pack_h2(v[2], v[3]));
        g_Bfl[idx] = make_uint2(pack_h2(r[0], r[1]), pack_h2(r[2], r[3]));
        return;
    }
    // bias blocks
    __shared__ float sw[4][NJ];
    int bb = b - 80;
    if (tid >= 128) return;
    int k = bb * 128 + tid;
    int warp = tid >> 5, lane = tid & 31;
    float bv = benc[k];
    float w[NJ];
#pragma unroll
    for (int j4 = 0; j4 < 5; j4++) {
        float4 v = *(const float4*)(Wcls + (size_t)k * 20 + j4 * 4);
        w[j4*4+0] = v.x; w[j4*4+1] = v.y; w[j4*4+2] = v.z; w[j4*4+3] = v.w;
    }
#pragma unroll
    for (int j4 = 0; j4 < 5; j4++) {
        float4 v = *(const float4*)(Wfl + (size_t)k * 20 + j4 * 4);
        w[20+j4*4+0] = v.x; w[20+j4*4+1] = v.y; w[20+j4*4+2] = v.z; w[20+j4*4+3] = v.w;
    }
#pragma unroll
    for (int j = 0; j < NJ; j++) {
        float s = bv * w[j];
#pragma unroll
        for (int o = 16; o > 0; o >>= 1) s += __shfl_xor_sync(0xffffffffu, s, o);
        if (lane == 0) sw[warp][j] = s;
    }
    __syncthreads();
    if (tid < NJ) {
        g_cpart[bb * NJ + tid] = (sw[0][tid] + sw[1][tid]) + (sw[2][tid] + sw[3][tid]);
        if (bb == 0) g_c[tid] = (tid < 20) ? bcls[tid] : bfl[tid - 20];
    }
}

// ---------------------------------------------------------------------------
// Main kernel: 128 rows x 40 cols per CTA, fp16 3-term mma.sync,
// x staged fp32 via double-buffered cp.async, fused dual-softmax epilogue.
// ---------------------------------------------------------------------------
__device__ __forceinline__ void stage_chunk(uint32_t smb, int buf, int c,
                                            const float* __restrict__ x,
                                            size_t growbase, int tid) {
    uint32_t xd = smb + (uint32_t)buf * BUFB;
#pragma unroll
    for (int it = 0; it < 8; it++) {
        int q = it * 256 + tid;
        int rw = q >> 4, c4 = q & 15;
        cp_async16(xd + (uint32_t)(rw * 272 + c4 * 16),
                   x + (growbase + rw) * KTOT + c * 64 + c4 * 4);
    }
    uint32_t bd = xd + XBYTES;
    const char* srcH = (const char*)(g_Bfh + (size_t)c * 640);
    const char* srcL = (const char*)(g_Bfl + (size_t)c * 640);
#pragma unroll
    for (int it = 0; it < 3; it++) {
        int q = it * 256 + tid;
        if (q < 320)      cp_async16(bd + (uint32_t)q * 16, srcH + q * 16);
        else if (q < 640) cp_async16(bd + 5120u + (uint32_t)(q - 320) * 16, srcL + (q - 320) * 16);
    }
}

__global__ __launch_bounds__(256, 1)
void mma_main_kernel(const float* __restrict__ x, float* __restrict__ out) {
    extern __shared__ char sm[];
    __shared__ float cb[NJ];
    const int tid = threadIdx.x;
    const int warp = tid >> 5, lane = tid & 31;
    const int c2 = (lane & 3) * 2;
    const size_t growbase = (size_t)blockIdx.x * 128;

    if (tid < NJ) {
        float s = g_c[tid];
#pragma unroll
        for (int p = 0; p < NBIAS; p++) s += g_cpart[p * NJ + tid];
        cb[tid] = s;
    }

    const uint32_t smb = smem_u32(sm);
    stage_chunk(smb, 0, 0, x, growbase, tid);
    cp_commit(); cp_wait0();
    __syncthreads();

    float acc1[NT][4], acc2[NT][4];
#pragma unroll
    for (int nt = 0; nt < NT; nt++)
#pragma unroll
        for (int e = 0; e < 4; e++) { acc1[nt][e] = 0.f; acc2[nt][e] = 0.f; }

    const uint32_t xoff = (uint32_t)((warp * 16 + (lane >> 2)) * 272 + c2 * 4);

    for (int c = 0; c < 32; c++) {
        int buf = c & 1;
        if (c + 1 < 32) { stage_chunk(smb, buf ^ 1, c + 1, x, growbase, tid); cp_commit(); }
        uint32_t base = smb + (uint32_t)buf * BUFB;
        uint32_t xa = base + xoff;
        uint32_t ba = base + XBYTES + (uint32_t)lane * 8;
#pragma unroll
        for (int s = 0; s < 4; s++) {
            float2 v00, v10, v01, v11;
            asm("ld.shared.v2.f32 {%0, %1}, [%2];" : "=f"(v00.x), "=f"(v00.y) : "r"(xa + s * 64));
            asm("ld.shared.v2.f32 {%0, %1}, [%2];" : "=f"(v10.x), "=f"(v10.y) : "r"(xa + s * 64 + 8 * 272));
            asm("ld.shared.v2.f32 {%0, %1}, [%2];" : "=f"(v01.x), "=f"(v01.y) : "r"(xa + s * 64 + 32));
            asm("ld.shared.v2.f32 {%0, %1}, [%2];" : "=f"(v11.x), "=f"(v11.y) : "r"(xa + s * 64 + 32 + 8 * 272));
            unsigned ah0, ah1, ah2, ah3, al0, al1, al2, al3;
            cvt_split_h(v00, ah0, al0);
            cvt_split_h(v10, ah1, al1);
            cvt_split_h(v01, ah2, al2);
            cvt_split_h(v11, ah3, al3);
#pragma unroll
            for (int nt = 0; nt < NT; nt++) {
                uint2 wh, wl;
                uint32_t fo = (uint32_t)((s * NT + nt) * 32) * 8;
                asm("ld.shared.v2.u32 {%0, %1}, [%2];" : "=r"(wh.x), "=r"(wh.y) : "r"(ba + fo));
                asm("ld.shared.v2.u32 {%0, %1}, [%2];" : "=r"(wl.x), "=r"(wl.y) : "r"(ba + fo + 5120));
                MMA_F16(acc1[nt], ah0, ah1, ah2, ah3, wh.x, wh.y);
                MMA_F16(acc2[nt], al0, al1, al2, al3, wh.x, wh.y);
                MMA_F16(acc2[nt], ah0, ah1, ah2, ah3, wl.x, wl.y);
            }
        }
        if (c + 1 < 32) cp_wait0();
        __syncthreads();
    }

    // ---- epilogue: combine scales, dual softmax + threshold ---------------
    int row0 = (int)growbase + warp * 16 + (lane >> 2);
    float scl[2];
    float ecls[2][6];
#pragma unroll
    for (int half = 0; half < 2; half++) {
        float m1 = -1e30f, m2 = -1e30f, mn2 = 1e30f;
#pragma unroll
        for (int nt = 0; nt < NT; nt++)
#pragma unroll
            for (int e = 0; e < 2; e++) {
                int j = nt * 8 + c2 + e;
                float v = acc1[nt][half * 2 + e] + acc2[nt][half * 2 + e] * RINV + cb[j];
                if (j < 20) m1 = fmaxf(m1, v);
                else { m2 = fmaxf(m2, v); mn2 = fminf(mn2, v); }
            }
        m1 = fmaxf(m1, __shfl_xor_sync(0xffffffffu, m1, 1));
        m1 = fmaxf(m1, __shfl_xor_sync(0xffffffffu, m1, 2));
        m2 = fmaxf(m2, __shfl_xor_sync(0xffffffffu, m2, 1));
        m2 = fmaxf(m2, __shfl_xor_sync(0xffffffffu, m2, 2));
        mn2 = fminf(mn2, __shfl_xor_sync(0xffffffffu, mn2, 1));
        mn2 = fminf(mn2, __shfl_xor_sync(0xffffffffu, mn2, 2));
        float s1 = 0.f, s2 = 0.f;
#pragma unroll
        for (int nt = 0; nt < NT; nt++)
#pragma unroll
            for (int e = 0; e < 2; e++) {
                int j = nt * 8 + c2 + e;
                float v = acc1[nt][half * 2 + e] + acc2[nt][half * 2 + e] * RINV + cb[j];
                if (j < 20) {
                    float ex = __expf(v - m1);
                    if (nt < 3) ecls[half][nt * 2 + e] = ex;
                    s1 += ex;
                } else {
                    s2 += __expf(v - m2);
                }
            }
        s1 += __shfl_xor_sync(0xffffffffu, s1, 1);
        s1 += __shfl_xor_sync(0xffffffffu, s1, 2);
        s2 += __shfl_xor_sync(0xffffffffu, s2, 1);
        s2 += __shfl_xor_sync(0xffffffffu, s2, 2);
        float pred = 1.0f / s1;
        float tau  = __expf(mn2 - m2) / s2;
        scl[half] = (pred >= tau + SMARGIN) ? pred : 0.0f;
    }
#pragma unroll
    for (int half = 0; half < 2; half++) {
        float* orow = out + (size_t)(row0 + half * 8) * 20;
#pragma unroll
        for (int nt = 0; nt < 3; nt++) {
            int j0 = nt * 8 + c2;
            if (j0 < 20)
                *(float2*)(orow + j0) = make_float2(ecls[half][nt * 2 + 0] * scl[half],
                                                    ecls[half][nt * 2 + 1] * scl[half]);
        }
    }
}

// ---------------------------------------------------------------------------
extern "C" void kernel_launch(void* const* d_in, const int* in_sizes, int n_in,
                              void* d_out, int out_size) {
    const float* x    = (const float*)d_in[0];
    const float* Wenc = (const float*)d_in[1];
    const float* benc = (const float*)d_in[2];
    const float* Wcls = (const float*)d_in[3];
    const float* bcls = (const float*)d_in[4];
    const float* Wfl  = (const float*)d_in[5];
    const float* bfl  = (const float*)d_in[6];
    float* out = (float*)d_out;
    int M = in_sizes[0] / KTOT;   // 16384

    static int smset = 0;
    if (!smset) {
        cudaFuncSetAttribute(mma_main_kernel,
                             cudaFuncAttributeMaxDynamicSharedMemorySize, 2 * BUFB);
        cudaFuncSetAttribute(prep_mma_kernel,
                             cudaFuncAttributeMaxDynamicSharedMemorySize, 2 * BUFB);
        smset = 1;
    }

    prep_mma_kernel<<<128, 256, 2 * BUFB>>>(Wenc, Wcls, Wfl);
    bsplit_bias_kernel<<<96, 256>>>(benc, Wcls, Wfl, bcls, bfl);
    mma_main_kernel<<<M / 128, 256, 2 * BUFB>>>(x, out);
}